// round 2
// baseline (speedup 1.0000x reference)
#include <cuda_runtime.h>

#define N_TOK 8192
#define DDIM  256
#define HDIM  64
#define NEXP  32
#define TILES 16      // 16 tiles * 64 tokens = 1024 tokens/expert max (mean 256, std ~16)

// ---------------- scratch (no allocations allowed) ----------------
__device__ int g_idx[N_TOK];
__device__ int g_counts[NEXP];     // zero-init; router tail resets to 0 each call
__device__ int g_off[NEXP + 1];
__device__ int g_cursor[NEXP];
__device__ int g_perm[N_TOK];
__device__ int g_done;             // zero-init; router tail resets to 0 each call

// ---------------- kernel 1: router + argmax + fused scan ----------------
// 1 warp per token. Lane l owns d in {4l..4l+3} U {128+4l..131+4l} (coalesced).
// Butterfly-reduce 32 expert partials; lane 0 argmaxes and histograms.
// The LAST warp to finish (done-counter) performs the 32-entry exclusive scan,
// seeds the scatter cursors, and resets counts/done for the next graph replay.
__global__ void __launch_bounds__(256) k_router(const float* __restrict__ x,
                                                const float* __restrict__ rw,
                                                const float* __restrict__ rb) {
    int warp = threadIdx.x >> 5;
    int lane = threadIdx.x & 31;
    int n = blockIdx.x * 8 + warp;

    const float4* X4 = (const float4*)x;
    const float4* W4 = (const float4*)rw;

    float4 x0 = X4[n * 64 + lane];
    float4 x1 = X4[n * 64 + 32 + lane];

    float p[NEXP];
#pragma unroll
    for (int e = 0; e < NEXP; e++) {
        float4 w0 = W4[e * 64 + lane];
        float4 w1 = W4[e * 64 + 32 + lane];
        p[e] = x0.x * w0.x + x0.y * w0.y + x0.z * w0.z + x0.w * w0.w
             + x1.x * w1.x + x1.y * w1.y + x1.z * w1.z + x1.w * w1.w;
    }

#pragma unroll
    for (int m = 1; m < 32; m <<= 1) {
#pragma unroll
        for (int e = 0; e < NEXP; e++)
            p[e] += __shfl_xor_sync(0xffffffffu, p[e], m);
    }

    if (lane == 0) {
        float best = p[0] + rb[0];
        int bi = 0;
#pragma unroll
        for (int e = 1; e < NEXP; e++) {
            float v = p[e] + rb[e];
            if (v > best) { best = v; bi = e; }   // strict > == first-max (jnp.argmax)
        }
        g_idx[n] = bi;
        atomicAdd(&g_counts[bi], 1);
        __threadfence();
        int fin = atomicAdd(&g_done, 1);
        if (fin == N_TOK - 1) {
            // all 8192 warps' count-atomics are globally visible (fence-fence sync)
            __threadfence();
            int c[NEXP];
#pragma unroll
            for (int e = 0; e < NEXP; e++) c[e] = __ldcg(&g_counts[e]);  // L2 direct, full MLP
            int s = 0;
#pragma unroll
            for (int e = 0; e < NEXP; e++) {
                g_off[e] = s;
                g_cursor[e] = s;
                g_counts[e] = 0;      // ready for next replay
                s += c[e];
            }
            g_off[NEXP] = s;
            g_done = 0;               // ready for next replay
        }
    }
}

// ---------------- kernel 2: scatter (block-aggregated counting sort) ----------------
// 256 tokens/block: smem histogram -> one global atomic per (block, expert)
// (1024 total, 32-deep contention) -> smem rank -> write. Per-expert SET is
// deterministic; intra-expert order is irrelevant to the output.
__global__ void __launch_bounds__(256) k_scatter() {
    __shared__ int hist[NEXP], sbase[NEXP], scur[NEXP];
    int tid = threadIdx.x;
    int n = blockIdx.x * 256 + tid;
    int e = g_idx[n];
    if (tid < NEXP) { hist[tid] = 0; scur[tid] = 0; }
    __syncthreads();
    atomicAdd(&hist[e], 1);
    __syncthreads();
    if (tid < NEXP) sbase[tid] = atomicAdd(&g_cursor[tid], hist[tid]);
    __syncthreads();
    int r = atomicAdd(&scur[e], 1);
    g_perm[sbase[e] + r] = n;
}

// ---------------- kernel 3: grouped expert FFN ----------------
// grid = (TILES, NEXP), 128 threads (4 warps -> one per SMSP, wid%4 mapping).
// CTA = 64 tokens of one expert, processed as two independent 32-token halves
// (hf = tid>>6) that SHARE the W1/W2 smem stage (loaded once per CTA).
// GEMM1: H[32x64] = X[32x256] @ W1[e]   per half (K chunked by 32)
// GEMM2: O[32x256] = relu(H) @ W2[e]    per half (4 chunks of 64 cols)
__global__ void __launch_bounds__(128) k_ffn(const float* __restrict__ x,
                                             const float* __restrict__ W1,
                                             const float* __restrict__ b1,
                                             const float* __restrict__ W2,
                                             const float* __restrict__ b2,
                                             float* __restrict__ out) {
    const int e    = blockIdx.y;
    const int tile = blockIdx.x;

    const int off0 = g_off[e];
    const int cnt  = g_off[e + 1] - off0;
    if (tile * 64 >= cnt) return;

    const int tid = threadIdx.x;
    const int hf  = tid >> 6;       // which 32-token half
    const int t   = tid & 63;
    const int tx  = t & 7;          // 8 col-groups
    const int ty  = t >> 3;         // 8 row-groups (4 tokens each)

    int rem = cnt - tile * 64 - hf * 32;
    const int nt = rem < 0 ? 0 : (rem > 32 ? 32 : rem);   // valid tokens in my half

    __shared__ int   toks[64];
    __shared__ float Xs[2][32][36];     // [half][k][token], padded
    __shared__ float Hs[2][HDIM][36];   // [half][h][token], padded
    __shared__ float Wbuf[64 * 64];     // GEMM1: [32][64]; GEMM2: [64][64]

    if (tid < 64) toks[tid] = g_perm[off0 + min(tile * 64 + tid, cnt - 1)];
    __syncthreads();

    const float4* Xg = (const float4*)x;

    float acc[4][8];
#pragma unroll
    for (int i = 0; i < 4; i++)
#pragma unroll
        for (int j = 0; j < 8; j++) acc[i][j] = 0.f;

    // ================= GEMM1: K = 256 in chunks of 32 =================
    const float4* Wg1 = (const float4*)(W1 + (size_t)e * DDIM * HDIM);
    for (int k0 = 0; k0 < DDIM; k0 += 32) {
        // stage X chunk, transposed: Xs[half][k][tok]  (512 float4 / 128 thr)
#pragma unroll
        for (int i = 0; i < 4; i++) {
            int lin = tid + i * 128;         // 0..511
            int tok = lin & 63;
            int kq  = lin >> 6;              // 0..7 (float4 within chunk)
            float4 v = Xg[(size_t)toks[tok] * 64 + (k0 >> 2) + kq];
            int hh = tok >> 5, tk = tok & 31;
            Xs[hh][kq * 4 + 0][tk] = v.x;
            Xs[hh][kq * 4 + 1][tk] = v.y;
            Xs[hh][kq * 4 + 2][tk] = v.z;
            Xs[hh][kq * 4 + 3][tk] = v.w;
        }
        // stage W1 chunk: rows k0..k0+31, all 64 h  (512 float4 / 128 thr)
#pragma unroll
        for (int i = 0; i < 4; i++) {
            int lin = tid + i * 128;         // 0..511
            int k   = lin >> 4;
            int h4  = lin & 15;
            *(float4*)&Wbuf[k * 64 + h4 * 4] = Wg1[(k0 << 4) + lin];
        }
        __syncthreads();

#pragma unroll
        for (int k = 0; k < 32; k++) {
            float4 a   = *(const float4*)&Xs[hf][k][ty * 4];
            float4 b0  = *(const float4*)&Wbuf[k * 64 + tx * 4];
            float4 b1v = *(const float4*)&Wbuf[k * 64 + 32 + tx * 4];
            float av[4] = {a.x, a.y, a.z, a.w};
            float bv[8] = {b0.x, b0.y, b0.z, b0.w, b1v.x, b1v.y, b1v.z, b1v.w};
#pragma unroll
            for (int i = 0; i < 4; i++)
#pragma unroll
                for (int j = 0; j < 8; j++) acc[i][j] += av[i] * bv[j];
        }
        __syncthreads();
    }

    // bias + relu -> Hs[half][h][tok] (transposed for GEMM2 a-loads)
    {
        float4 bb0 = *(const float4*)&b1[e * HDIM + tx * 4];
        float4 bb1 = *(const float4*)&b1[e * HDIM + 32 + tx * 4];
        float bb[8] = {bb0.x, bb0.y, bb0.z, bb0.w, bb1.x, bb1.y, bb1.z, bb1.w};
#pragma unroll
        for (int i = 0; i < 4; i++) {
            int tok = ty * 4 + i;
#pragma unroll
            for (int j = 0; j < 8; j++) {
                float v = acc[i][j] + bb[j];
                int h = (j < 4) ? (tx * 4 + j) : (32 + tx * 4 + (j - 4));
                Hs[hf][h][tok] = v > 0.f ? v : 0.f;
            }
        }
    }

    // ================= GEMM2: 4 chunks of 64 output cols =================
    const float4* W2g = (const float4*)(W2 + (size_t)e * HDIM * DDIM);
    for (int c = 0; c < 4; c++) {
        __syncthreads();   // Hs ready (first iter) / Wbuf reads done (later iters)
#pragma unroll
        for (int i = 0; i < 8; i++) {
            int lin = tid + i * 128;         // 0..1023
            int k   = lin >> 4;
            int n4  = lin & 15;
            *(float4*)&Wbuf[k * 64 + n4 * 4] = W2g[k * 64 + c * 16 + n4];
        }
        __syncthreads();

#pragma unroll
        for (int i = 0; i < 4; i++)
#pragma unroll
            for (int j = 0; j < 8; j++) acc[i][j] = 0.f;

#pragma unroll 8
        for (int k = 0; k < HDIM; k++) {
            float4 a   = *(const float4*)&Hs[hf][k][ty * 4];
            float4 b0  = *(const float4*)&Wbuf[k * 64 + tx * 4];
            float4 b1v = *(const float4*)&Wbuf[k * 64 + 32 + tx * 4];
            float av[4] = {a.x, a.y, a.z, a.w};
            float bv[8] = {b0.x, b0.y, b0.z, b0.w, b1v.x, b1v.y, b1v.z, b1v.w};
#pragma unroll
            for (int i = 0; i < 4; i++)
#pragma unroll
                for (int j = 0; j < 8; j++) acc[i][j] += av[i] * bv[j];
        }

        // epilogue: bias + relu + store
        float4 c0 = *(const float4*)&b2[e * DDIM + c * 64 + tx * 4];
        float4 c1 = *(const float4*)&b2[e * DDIM + c * 64 + 32 + tx * 4];
#pragma unroll
        for (int i = 0; i < 4; i++) {
            int ti = ty * 4 + i;
            if (ti < nt) {
                size_t row = (size_t)toks[hf * 32 + ti] * DDIM;
                float4 r0, r1;
                r0.x = fmaxf(acc[i][0] + c0.x, 0.f);
                r0.y = fmaxf(acc[i][1] + c0.y, 0.f);
                r0.z = fmaxf(acc[i][2] + c0.z, 0.f);
                r0.w = fmaxf(acc[i][3] + c0.w, 0.f);
                r1.x = fmaxf(acc[i][4] + c1.x, 0.f);
                r1.y = fmaxf(acc[i][5] + c1.y, 0.f);
                r1.z = fmaxf(acc[i][6] + c1.z, 0.f);
                r1.w = fmaxf(acc[i][7] + c1.w, 0.f);
                *(float4*)&out[row + c * 64 + tx * 4] = r0;
                *(float4*)&out[row + c * 64 + 32 + tx * 4] = r1;
            }
        }
    }
}

// ---------------- launch ----------------
extern "C" void kernel_launch(void* const* d_in, const int* in_sizes, int n_in,
                              void* d_out, int out_size) {
    const float* x   = (const float*)d_in[0];
    const float* rw  = (const float*)d_in[1];
    const float* rb  = (const float*)d_in[2];
    const float* W1  = (const float*)d_in[3];
    const float* b1  = (const float*)d_in[4];
    const float* W2  = (const float*)d_in[5];
    const float* b2  = (const float*)d_in[6];
    float* out = (float*)d_out;

    k_router<<<N_TOK / 8, 256>>>(x, rw, rb);
    k_scatter<<<N_TOK / 256, 256>>>();
    dim3 grid(TILES, NEXP);
    k_ffn<<<grid, 128>>>(x, W1, b1, W2, b2, out);
}

// round 3
// speedup vs baseline: 1.9875x; 1.9875x over previous
#include <cuda_runtime.h>

#define N_TOK 8192
#define DDIM  256
#define HDIM  64
#define NEXP  32
#define FFN_CTAS 160   // >= max tiles: 8192/64=128 full + <=31 partial tails

// ---------------- scratch (no allocations allowed) ----------------
__device__ int g_idx[N_TOK];
__device__ int g_counts[NEXP];     // zero at init; k_scan resets each call
__device__ int g_off[NEXP + 1];
__device__ int g_cursor[NEXP];
__device__ int g_perm[N_TOK];

// ---------------- kernel 1: router + argmax ----------------
// 1 warp per token. Lane l owns d in {4l..4l+3} U {128+4l..131+4l} (coalesced).
// Reduce-scatter transpose (31 SHFL): lane l ends holding the full logit of
// expert l. Then 10-SHFL warp argmax (first-max ties). Histogram = RED to 32
// addresses (no return -> no serialization hot spot).
__global__ void __launch_bounds__(256) k_router(const float* __restrict__ x,
                                                const float* __restrict__ rw,
                                                const float* __restrict__ rb) {
    int warp = threadIdx.x >> 5;
    int lane = threadIdx.x & 31;
    int n = blockIdx.x * 8 + warp;

    const float4* X4 = (const float4*)x;
    const float4* W4 = (const float4*)rw;

    float4 x0 = X4[n * 64 + lane];
    float4 x1 = X4[n * 64 + 32 + lane];

    float p[NEXP];
#pragma unroll
    for (int e = 0; e < NEXP; e++) {
        float4 w0 = W4[e * 64 + lane];
        float4 w1 = W4[e * 64 + 32 + lane];
        p[e] = x0.x * w0.x + x0.y * w0.y + x0.z * w0.z + x0.w * w0.w
             + x1.x * w1.x + x1.y * w1.y + x1.z * w1.z + x1.w * w1.w;
    }

    // reduce-scatter transpose: after this, p[0] on lane l = logit of expert l
#pragma unroll
    for (int off = 16; off > 0; off >>= 1) {
        bool hi = (lane & off) != 0;
#pragma unroll
        for (int i = 0; i < 16; i++) {
            if (i < off) {
                float sel = hi ? p[i] : p[i + off];
                float got = __shfl_xor_sync(0xffffffffu, sel, off);
                p[i] = (hi ? p[i + off] : p[i]) + got;
            }
        }
    }

    float v  = p[0] + rb[lane];
    int   bi = lane;
#pragma unroll
    for (int off = 16; off > 0; off >>= 1) {
        float ov = __shfl_xor_sync(0xffffffffu, v, off);
        int   oi = __shfl_xor_sync(0xffffffffu, bi, off);
        if (ov > v || (ov == v && oi < bi)) { v = ov; bi = oi; }  // first-max
    }

    if (lane == 0) {
        g_idx[n] = bi;
        atomicAdd(&g_counts[bi], 1);   // return unused -> RED
    }
}

// ---------------- kernel 2: 32-entry exclusive scan (1 warp) ----------------
__global__ void k_scan() {
    int lane = threadIdx.x;
    int c = g_counts[lane];
    int s = c;
#pragma unroll
    for (int off = 1; off < 32; off <<= 1) {
        int t = __shfl_up_sync(0xffffffffu, s, off);
        if (lane >= off) s += t;
    }
    g_off[lane]    = s - c;
    g_cursor[lane] = s - c;
    if (lane == 31) g_off[NEXP] = s;
    g_counts[lane] = 0;                // ready for next graph replay
}

// ---------------- kernel 3: scatter (block-aggregated counting sort) ----------------
__global__ void __launch_bounds__(256) k_scatter() {
    __shared__ int hist[NEXP], sbase[NEXP], scur[NEXP];
    int tid = threadIdx.x;
    int n = blockIdx.x * 256 + tid;
    int e = g_idx[n];
    if (tid < NEXP) { hist[tid] = 0; scur[tid] = 0; }
    __syncthreads();
    atomicAdd(&hist[e], 1);
    __syncthreads();
    if (tid < NEXP) sbase[tid] = atomicAdd(&g_cursor[tid], hist[tid]);
    __syncthreads();
    int r = atomicAdd(&scur[e], 1);
    g_perm[sbase[e] + r] = n;
}

// ---------------- kernel 4: grouped expert FFN ----------------
// 1-D grid of uniform-work CTAs; CTA derives (expert, tile) from g_off.
// 128 threads (1 warp per SMSP). CTA = 64 tokens as two independent 32-token
// halves sharing one W1/W2 smem stage.
__global__ void __launch_bounds__(128) k_ffn(const float* __restrict__ x,
                                             const float* __restrict__ W1,
                                             const float* __restrict__ b1,
                                             const float* __restrict__ W2,
                                             const float* __restrict__ b2,
                                             float* __restrict__ out) {
    // map blockIdx.x -> (expert e, tile) over variable per-expert tile counts
    int e = -1, tile = 0;
    {
        int t = blockIdx.x, acc = 0, prev = g_off[0];
#pragma unroll
        for (int ee = 0; ee < NEXP; ee++) {
            int nxt = g_off[ee + 1];
            int tiles_e = (nxt - prev + 63) >> 6;
            if (e < 0 && t < acc + tiles_e) { e = ee; tile = t - acc; }
            acc += tiles_e;
            prev = nxt;
        }
        if (e < 0) return;   // beyond total tiles this replay
    }

    const int off0 = g_off[e];
    const int cnt  = g_off[e + 1] - off0;

    const int tid = threadIdx.x;
    const int hf  = tid >> 6;       // which 32-token half
    const int t   = tid & 63;
    const int tx  = t & 7;          // 8 col-groups
    const int ty  = t >> 3;         // 8 row-groups (4 tokens each)

    int rem = cnt - tile * 64 - hf * 32;
    const int nt = rem < 0 ? 0 : (rem > 32 ? 32 : rem);   // valid tokens in my half

    __shared__ int   toks[64];
    __shared__ float Xs[2][32][36];     // [half][k][token], padded
    __shared__ float Hs[2][HDIM][36];   // [half][h][token], padded
    __shared__ float Wbuf[64 * 64];     // GEMM1: [32][64]; GEMM2: [64][64]

    if (tid < 64) toks[tid] = g_perm[off0 + min(tile * 64 + tid, cnt - 1)];
    __syncthreads();

    const float4* Xg = (const float4*)x;

    float acc[4][8];
#pragma unroll
    for (int i = 0; i < 4; i++)
#pragma unroll
        for (int j = 0; j < 8; j++) acc[i][j] = 0.f;

    // ================= GEMM1: K = 256 in chunks of 32 =================
    const float4* Wg1 = (const float4*)(W1 + (size_t)e * DDIM * HDIM);
    for (int k0 = 0; k0 < DDIM; k0 += 32) {
        // stage X chunk, transposed: Xs[half][k][tok]  (512 float4 / 128 thr)
#pragma unroll
        for (int i = 0; i < 4; i++) {
            int lin = tid + i * 128;         // 0..511
            int tok = lin & 63;
            int kq  = lin >> 6;              // 0..7 (float4 within chunk)
            float4 v = Xg[(size_t)toks[tok] * 64 + (k0 >> 2) + kq];
            int hh = tok >> 5, tk = tok & 31;
            Xs[hh][kq * 4 + 0][tk] = v.x;
            Xs[hh][kq * 4 + 1][tk] = v.y;
            Xs[hh][kq * 4 + 2][tk] = v.z;
            Xs[hh][kq * 4 + 3][tk] = v.w;
        }
        // stage W1 chunk: rows k0..k0+31, all 64 h  (512 float4 / 128 thr)
#pragma unroll
        for (int i = 0; i < 4; i++) {
            int lin = tid + i * 128;         // 0..511
            int k   = lin >> 4;
            int h4  = lin & 15;
            *(float4*)&Wbuf[k * 64 + h4 * 4] = Wg1[(k0 << 4) + lin];
        }
        __syncthreads();

#pragma unroll
        for (int k = 0; k < 32; k++) {
            float4 a   = *(const float4*)&Xs[hf][k][ty * 4];
            float4 b0  = *(const float4*)&Wbuf[k * 64 + tx * 4];
            float4 b1v = *(const float4*)&Wbuf[k * 64 + 32 + tx * 4];
            float av[4] = {a.x, a.y, a.z, a.w};
            float bv[8] = {b0.x, b0.y, b0.z, b0.w, b1v.x, b1v.y, b1v.z, b1v.w};
#pragma unroll
            for (int i = 0; i < 4; i++)
#pragma unroll
                for (int j = 0; j < 8; j++) acc[i][j] += av[i] * bv[j];
        }
        __syncthreads();
    }

    // bias + relu -> Hs[half][h][tok] (transposed for GEMM2 a-loads)
    {
        float4 bb0 = *(const float4*)&b1[e * HDIM + tx * 4];
        float4 bb1 = *(const float4*)&b1[e * HDIM + 32 + tx * 4];
        float bb[8] = {bb0.x, bb0.y, bb0.z, bb0.w, bb1.x, bb1.y, bb1.z, bb1.w};
#pragma unroll
        for (int i = 0; i < 4; i++) {
            int tok = ty * 4 + i;
#pragma unroll
            for (int j = 0; j < 8; j++) {
                float v = acc[i][j] + bb[j];
                int h = (j < 4) ? (tx * 4 + j) : (32 + tx * 4 + (j - 4));
                Hs[hf][h][tok] = v > 0.f ? v : 0.f;
            }
        }
    }

    // ================= GEMM2: 4 chunks of 64 output cols =================
    const float4* W2g = (const float4*)(W2 + (size_t)e * HDIM * DDIM);
    for (int c = 0; c < 4; c++) {
        __syncthreads();   // Hs ready (first iter) / Wbuf reads done (later iters)
#pragma unroll
        for (int i = 0; i < 8; i++) {
            int lin = tid + i * 128;         // 0..1023
            int k   = lin >> 4;
            int n4  = lin & 15;
            *(float4*)&Wbuf[k * 64 + n4 * 4] = W2g[k * 64 + c * 16 + n4];
        }
        __syncthreads();

#pragma unroll
        for (int i = 0; i < 4; i++)
#pragma unroll
            for (int j = 0; j < 8; j++) acc[i][j] = 0.f;

#pragma unroll 8
        for (int k = 0; k < HDIM; k++) {
            float4 a   = *(const float4*)&Hs[hf][k][ty * 4];
            float4 b0  = *(const float4*)&Wbuf[k * 64 + tx * 4];
            float4 b1v = *(const float4*)&Wbuf[k * 64 + 32 + tx * 4];
            float av[4] = {a.x, a.y, a.z, a.w};
            float bv[8] = {b0.x, b0.y, b0.z, b0.w, b1v.x, b1v.y, b1v.z, b1v.w};
#pragma unroll
            for (int i = 0; i < 4; i++)
#pragma unroll
                for (int j = 0; j < 8; j++) acc[i][j] += av[i] * bv[j];
        }

        // epilogue: bias + relu + store
        float4 c0 = *(const float4*)&b2[e * DDIM + c * 64 + tx * 4];
        float4 c1 = *(const float4*)&b2[e * DDIM + c * 64 + 32 + tx * 4];
#pragma unroll
        for (int i = 0; i < 4; i++) {
            int ti = ty * 4 + i;
            if (ti < nt) {
                size_t row = (size_t)toks[hf * 32 + ti] * DDIM;
                float4 r0, r1;
                r0.x = fmaxf(acc[i][0] + c0.x, 0.f);
                r0.y = fmaxf(acc[i][1] + c0.y, 0.f);
                r0.z = fmaxf(acc[i][2] + c0.z, 0.f);
                r0.w = fmaxf(acc[i][3] + c0.w, 0.f);
                r1.x = fmaxf(acc[i][4] + c1.x, 0.f);
                r1.y = fmaxf(acc[i][5] + c1.y, 0.f);
                r1.z = fmaxf(acc[i][6] + c1.z, 0.f);
                r1.w = fmaxf(acc[i][7] + c1.w, 0.f);
                *(float4*)&out[row + c * 64 + tx * 4] = r0;
                *(float4*)&out[row + c * 64 + 32 + tx * 4] = r1;
            }
        }
    }
}

// ---------------- launch ----------------
extern "C" void kernel_launch(void* const* d_in, const int* in_sizes, int n_in,
                              void* d_out, int out_size) {
    const float* x   = (const float*)d_in[0];
    const float* rw  = (const float*)d_in[1];
    const float* rb  = (const float*)d_in[2];
    const float* W1  = (const float*)d_in[3];
    const float* b1  = (const float*)d_in[4];
    const float* W2  = (const float*)d_in[5];
    const float* b2  = (const float*)d_in[6];
    float* out = (float*)d_out;

    k_router<<<N_TOK / 8, 256>>>(x, rw, rb);
    k_scan<<<1, 32>>>();
    k_scatter<<<N_TOK / 256, 256>>>();
    k_ffn<<<FFN_CTAS, 128>>>(x, W1, b1, W2, b2, out);
}

// round 4
// speedup vs baseline: 2.0857x; 1.0494x over previous
#include <cuda_runtime.h>

#define N_TOK 8192
#define DDIM  256
#define HDIM  64
#define NEXP  32
#define TM    32        // tokens per ffn tile
#define FFN_CTAS 288    // >= max tiles: 8192/32=256 full + <=31 partial tails

// ---------------- scratch (no allocations allowed) ----------------
__device__ int g_idx[N_TOK];
__device__ int g_counts[NEXP];     // zero at init; k_scan resets each call
__device__ int g_off[NEXP + 1];
__device__ int g_cursor[NEXP];
__device__ int g_perm[N_TOK];

// ---------------- kernel 1: router + argmax ----------------
// 1 warp per token. Reduce-scatter transpose (31 SHFL) -> lane l holds logit
// of expert l; 10-SHFL first-max argmax; RED histogram (32 addresses).
__global__ void __launch_bounds__(256) k_router(const float* __restrict__ x,
                                                const float* __restrict__ rw,
                                                const float* __restrict__ rb) {
    int warp = threadIdx.x >> 5;
    int lane = threadIdx.x & 31;
    int n = blockIdx.x * 8 + warp;

    const float4* X4 = (const float4*)x;
    const float4* W4 = (const float4*)rw;

    float4 x0 = X4[n * 64 + lane];
    float4 x1 = X4[n * 64 + 32 + lane];

    float p[NEXP];
#pragma unroll
    for (int e = 0; e < NEXP; e++) {
        float4 w0 = W4[e * 64 + lane];
        float4 w1 = W4[e * 64 + 32 + lane];
        p[e] = x0.x * w0.x + x0.y * w0.y + x0.z * w0.z + x0.w * w0.w
             + x1.x * w1.x + x1.y * w1.y + x1.z * w1.z + x1.w * w1.w;
    }

#pragma unroll
    for (int off = 16; off > 0; off >>= 1) {
        bool hi = (lane & off) != 0;
#pragma unroll
        for (int i = 0; i < 16; i++) {
            if (i < off) {
                float sel = hi ? p[i] : p[i + off];
                float got = __shfl_xor_sync(0xffffffffu, sel, off);
                p[i] = (hi ? p[i + off] : p[i]) + got;
            }
        }
    }

    float v  = p[0] + rb[lane];
    int   bi = lane;
#pragma unroll
    for (int off = 16; off > 0; off >>= 1) {
        float ov = __shfl_xor_sync(0xffffffffu, v, off);
        int   oi = __shfl_xor_sync(0xffffffffu, bi, off);
        if (ov > v || (ov == v && oi < bi)) { v = ov; bi = oi; }  // first-max
    }

    if (lane == 0) {
        g_idx[n] = bi;
        atomicAdd(&g_counts[bi], 1);   // return unused -> RED
    }
}

// ---------------- kernel 2: 32-entry exclusive scan (1 warp) ----------------
__global__ void k_scan() {
    int lane = threadIdx.x;
    int c = g_counts[lane];
    int s = c;
#pragma unroll
    for (int off = 1; off < 32; off <<= 1) {
        int t = __shfl_up_sync(0xffffffffu, s, off);
        if (lane >= off) s += t;
    }
    g_off[lane]    = s - c;
    g_cursor[lane] = s - c;
    if (lane == 31) g_off[NEXP] = s;
    g_counts[lane] = 0;                // ready for next graph replay
}

// ---------------- kernel 3: scatter (block-aggregated counting sort) ----------------
__global__ void __launch_bounds__(256) k_scatter() {
    __shared__ int hist[NEXP], sbase[NEXP], scur[NEXP];
    int tid = threadIdx.x;
    int n = blockIdx.x * 256 + tid;
    int e = g_idx[n];
    if (tid < NEXP) { hist[tid] = 0; scur[tid] = 0; }
    __syncthreads();
    atomicAdd(&hist[e], 1);
    __syncthreads();
    if (tid < NEXP) sbase[tid] = atomicAdd(&g_cursor[tid], hist[tid]);
    __syncthreads();
    int r = atomicAdd(&scur[e], 1);
    g_perm[sbase[e] + r] = n;
}

// ---------------- kernel 4: grouped expert FFN ----------------
// ~288 CTAs of 128 threads, 32 tokens each -> 2 CTAs/SM in one wave
// (2 warps/SMSP + cross-CTA overlap at barriers).
// Thread tile 4 tokens x 4 h: per k, 2 LDS.128 + 16 FFMA (fma-bound).
__global__ void __launch_bounds__(128) k_ffn(const float* __restrict__ x,
                                             const float* __restrict__ W1,
                                             const float* __restrict__ b1,
                                             const float* __restrict__ W2,
                                             const float* __restrict__ b2,
                                             float* __restrict__ out) {
    // map blockIdx.x -> (expert e, tile) over variable per-expert tile counts
    int e = -1, tile = 0;
    {
        int t = blockIdx.x, acc = 0, prev = g_off[0];
#pragma unroll
        for (int ee = 0; ee < NEXP; ee++) {
            int nxt = g_off[ee + 1];
            int tiles_e = (nxt - prev + TM - 1) >> 5;
            if (e < 0 && t < acc + tiles_e) { e = ee; tile = t - acc; }
            acc += tiles_e;
            prev = nxt;
        }
        if (e < 0) return;
    }

    const int off0 = g_off[e];
    const int cnt  = g_off[e + 1] - off0;

    const int tid = threadIdx.x;
    const int tx  = tid & 15;        // 16 h-groups of 4
    const int ty  = tid >> 4;        // 8 token-groups of 4

    int rem = cnt - tile * TM;
    const int nt = rem > TM ? TM : rem;   // valid tokens in this tile (>=1)

    __shared__ int   toks[TM];
    __shared__ float Xs[32][36];      // [k][token], padded (rows 16B-aligned)
    __shared__ float Hs[HDIM][36];    // [h][token], padded
    __shared__ float Wbuf[64 * 64];   // GEMM1: [32][64]; GEMM2: [64][64]

    if (tid < TM) toks[tid] = g_perm[off0 + min(tile * TM + tid, cnt - 1)];
    __syncthreads();

    const float4* Xg = (const float4*)x;

    float acc[4][4];
#pragma unroll
    for (int i = 0; i < 4; i++)
#pragma unroll
        for (int j = 0; j < 4; j++) acc[i][j] = 0.f;

    // ================= GEMM1: K = 256 in chunks of 32 =================
    const float4* Wg1 = (const float4*)(W1 + (size_t)e * DDIM * HDIM);
    for (int k0 = 0; k0 < DDIM; k0 += 32) {
        // stage X chunk, transposed: Xs[k][tok]  (256 float4 / 128 thr)
#pragma unroll
        for (int i = 0; i < 2; i++) {
            int lin = tid + i * 128;         // 0..255
            int tok = lin & 31;
            int kq  = lin >> 5;              // 0..7 (float4 within chunk)
            float4 v = Xg[(size_t)toks[tok] * 64 + (k0 >> 2) + kq];
            Xs[kq * 4 + 0][tok] = v.x;
            Xs[kq * 4 + 1][tok] = v.y;
            Xs[kq * 4 + 2][tok] = v.z;
            Xs[kq * 4 + 3][tok] = v.w;
        }
        // stage W1 chunk: rows k0..k0+31, all 64 h  (512 float4 / 128 thr)
#pragma unroll
        for (int i = 0; i < 4; i++) {
            int lin = tid + i * 128;         // 0..511
            int k   = lin >> 4;
            int h4  = lin & 15;
            *(float4*)&Wbuf[k * 64 + h4 * 4] = Wg1[(k0 << 4) + lin];
        }
        __syncthreads();

#pragma unroll
        for (int k = 0; k < 32; k++) {
            float4 a = *(const float4*)&Xs[k][ty * 4];
            float4 b = *(const float4*)&Wbuf[k * 64 + tx * 4];
            float av[4] = {a.x, a.y, a.z, a.w};
            float bv[4] = {b.x, b.y, b.z, b.w};
#pragma unroll
            for (int i = 0; i < 4; i++)
#pragma unroll
                for (int j = 0; j < 4; j++) acc[i][j] += av[i] * bv[j];
        }
        __syncthreads();
    }

    // bias + relu -> Hs[h][tok] (transposed for GEMM2 a-loads)
    {
        float4 bb = *(const float4*)&b1[e * HDIM + tx * 4];
        float bv[4] = {bb.x, bb.y, bb.z, bb.w};
#pragma unroll
        for (int i = 0; i < 4; i++) {
            int tok = ty * 4 + i;
#pragma unroll
            for (int j = 0; j < 4; j++) {
                float v = acc[i][j] + bv[j];
                Hs[tx * 4 + j][tok] = v > 0.f ? v : 0.f;
            }
        }
    }

    // ================= GEMM2: 4 chunks of 64 output cols =================
    const float4* W2g = (const float4*)(W2 + (size_t)e * HDIM * DDIM);
    for (int c = 0; c < 4; c++) {
        __syncthreads();   // Hs ready (first iter) / Wbuf reads done (later)
#pragma unroll
        for (int i = 0; i < 8; i++) {
            int lin = tid + i * 128;         // 0..1023
            int k   = lin >> 4;
            int n4  = lin & 15;
            *(float4*)&Wbuf[k * 64 + n4 * 4] = W2g[k * 64 + c * 16 + n4];
        }
        __syncthreads();

#pragma unroll
        for (int i = 0; i < 4; i++)
#pragma unroll
            for (int j = 0; j < 4; j++) acc[i][j] = 0.f;

#pragma unroll 8
        for (int k = 0; k < HDIM; k++) {
            float4 a = *(const float4*)&Hs[k][ty * 4];
            float4 b = *(const float4*)&Wbuf[k * 64 + tx * 4];
            float av[4] = {a.x, a.y, a.z, a.w};
            float bv[4] = {b.x, b.y, b.z, b.w};
#pragma unroll
            for (int i = 0; i < 4; i++)
#pragma unroll
                for (int j = 0; j < 4; j++) acc[i][j] += av[i] * bv[j];
        }

        // epilogue: bias + relu + store
        float4 cb = *(const float4*)&b2[e * DDIM + c * 64 + tx * 4];
#pragma unroll
        for (int i = 0; i < 4; i++) {
            int ti = ty * 4 + i;
            if (ti < nt) {
                size_t row = (size_t)toks[ti] * DDIM;
                float4 r;
                r.x = fmaxf(acc[i][0] + cb.x, 0.f);
                r.y = fmaxf(acc[i][1] + cb.y, 0.f);
                r.z = fmaxf(acc[i][2] + cb.z, 0.f);
                r.w = fmaxf(acc[i][3] + cb.w, 0.f);
                *(float4*)&out[row + c * 64 + tx * 4] = r;
            }
        }
    }
}

// ---------------- launch ----------------
extern "C" void kernel_launch(void* const* d_in, const int* in_sizes, int n_in,
                              void* d_out, int out_size) {
    const float* x   = (const float*)d_in[0];
    const float* rw  = (const float*)d_in[1];
    const float* rb  = (const float*)d_in[2];
    const float* W1  = (const float*)d_in[3];
    const float* b1  = (const float*)d_in[4];
    const float* W2  = (const float*)d_in[5];
    const float* b2  = (const float*)d_in[6];
    float* out = (float*)d_out;

    k_router<<<N_TOK / 8, 256>>>(x, rw, rb);
    k_scan<<<1, 32>>>();
    k_scatter<<<N_TOK / 256, 256>>>();
    k_ffn<<<FFN_CTAS, 128>>>(x, W1, b1, W2, b2, out);
}

// round 5
// speedup vs baseline: 2.1069x; 1.0101x over previous
#include <cuda_runtime.h>

#define N_TOK 8192
#define DDIM  256
#define HDIM  64
#define NEXP  32
#define TM    32        // tokens per ffn tile
#define FFN_CTAS 288    // >= max tiles: 8192/32=256 full + <=31 partial tails

// ---------------- scratch (no allocations allowed) ----------------
__device__ int g_idx[N_TOK];
__device__ int g_counts[NEXP];     // zero at init; k_scan resets each call
__device__ int g_off[NEXP + 1];
__device__ int g_cursor[NEXP];
__device__ int g_perm[N_TOK];

// ---------------- kernel 1: router + argmax ----------------
__global__ void __launch_bounds__(256) k_router(const float* __restrict__ x,
                                                const float* __restrict__ rw,
                                                const float* __restrict__ rb) {
    int warp = threadIdx.x >> 5;
    int lane = threadIdx.x & 31;
    int n = blockIdx.x * 8 + warp;

    const float4* X4 = (const float4*)x;
    const float4* W4 = (const float4*)rw;

    float4 x0 = X4[n * 64 + lane];
    float4 x1 = X4[n * 64 + 32 + lane];

    float p[NEXP];
#pragma unroll
    for (int e = 0; e < NEXP; e++) {
        float4 w0 = W4[e * 64 + lane];
        float4 w1 = W4[e * 64 + 32 + lane];
        p[e] = x0.x * w0.x + x0.y * w0.y + x0.z * w0.z + x0.w * w0.w
             + x1.x * w1.x + x1.y * w1.y + x1.z * w1.z + x1.w * w1.w;
    }

    // reduce-scatter transpose: lane l ends holding full logit of expert l
#pragma unroll
    for (int off = 16; off > 0; off >>= 1) {
        bool hi = (lane & off) != 0;
#pragma unroll
        for (int i = 0; i < 16; i++) {
            if (i < off) {
                float sel = hi ? p[i] : p[i + off];
                float got = __shfl_xor_sync(0xffffffffu, sel, off);
                p[i] = (hi ? p[i + off] : p[i]) + got;
            }
        }
    }

    float v  = p[0] + rb[lane];
    int   bi = lane;
#pragma unroll
    for (int off = 16; off > 0; off >>= 1) {
        float ov = __shfl_xor_sync(0xffffffffu, v, off);
        int   oi = __shfl_xor_sync(0xffffffffu, bi, off);
        if (ov > v || (ov == v && oi < bi)) { v = ov; bi = oi; }  // first-max
    }

    if (lane == 0) {
        g_idx[n] = bi;
        atomicAdd(&g_counts[bi], 1);   // return unused -> RED
    }
}

// ---------------- kernel 2: 32-entry exclusive scan (1 warp) ----------------
__global__ void k_scan() {
    int lane = threadIdx.x;
    int c = g_counts[lane];
    int s = c;
#pragma unroll
    for (int off = 1; off < 32; off <<= 1) {
        int t = __shfl_up_sync(0xffffffffu, s, off);
        if (lane >= off) s += t;
    }
    g_off[lane]    = s - c;
    g_cursor[lane] = s - c;
    if (lane == 31) g_off[NEXP] = s;
    g_counts[lane] = 0;                // ready for next graph replay
}

// ---------------- kernel 3: scatter (block-aggregated counting sort) ----------------
__global__ void __launch_bounds__(256) k_scatter() {
    __shared__ int hist[NEXP], sbase[NEXP], scur[NEXP];
    int tid = threadIdx.x;
    int n = blockIdx.x * 256 + tid;
    int e = g_idx[n];
    if (tid < NEXP) { hist[tid] = 0; scur[tid] = 0; }
    __syncthreads();
    atomicAdd(&hist[e], 1);
    __syncthreads();
    if (tid < NEXP) sbase[tid] = atomicAdd(&g_cursor[tid], hist[tid]);
    __syncthreads();
    int r = atomicAdd(&scur[e], 1);
    g_perm[sbase[e] + r] = n;
}

// ---------------- kernel 4: grouped expert FFN (software-pipelined) ----------------
// 288 CTAs x 128 thr, 32 tokens/CTA (2 CTAs/SM). Double-buffered smem arena;
// per chunk: STS(prefetched regs) -> LDG(next chunk) -> 1 barrier -> compute.
// LDG latency hides under the ~2K-cyc chunk compute; 13 barriers/CTA total.
__global__ void __launch_bounds__(128) k_ffn(const float* __restrict__ x,
                                             const float* __restrict__ W1,
                                             const float* __restrict__ b1,
                                             const float* __restrict__ W2,
                                             const float* __restrict__ b2,
                                             float* __restrict__ out) {
    // map blockIdx.x -> (expert e, tile)
    int e = -1, tile = 0;
    {
        int t = blockIdx.x, acc = 0, prev = g_off[0];
#pragma unroll
        for (int ee = 0; ee < NEXP; ee++) {
            int nxt = g_off[ee + 1];
            int tiles_e = (nxt - prev + TM - 1) >> 5;
            if (e < 0 && t < acc + tiles_e) { e = ee; tile = t - acc; }
            acc += tiles_e;
            prev = nxt;
        }
        if (e < 0) return;
    }

    const int off0 = g_off[e];
    const int cnt  = g_off[e + 1] - off0;

    const int tid = threadIdx.x;
    const int tx  = tid & 15;        // 16 h-groups of 4
    const int ty  = tid >> 4;        // 8 token-groups of 4

    int rem = cnt - tile * TM;
    const int nt = rem > TM ? TM : rem;

    __shared__ int   toks[TM];
    __shared__ float Hs[HDIM][36];       // [h][tok], padded
    __shared__ float arena[8192];        // 32KB union:
    // GEMM1: Xs[b][k][t] = arena[b*1152 + k*36 + t]   (b<2, k<32, t<32)
    //        Wb1[b][k][h] = arena[2304 + b*2048 + k*64 + h]
    // GEMM2: Wb2[b][k][n] = arena[b*4096 + k*64 + n]
#define XS(b,k,t)  arena[(b)*1152 + (k)*36 + (t)]
#define WB1(b,k,h) arena[2304 + (b)*2048 + (k)*64 + (h)]
#define WB2(b,k,nn) arena[(b)*4096 + (k)*64 + (nn)]

    if (tid < TM) toks[tid] = g_perm[off0 + min(tile * TM + tid, cnt - 1)];
    __syncthreads();

    const float4* Xg  = (const float4*)x;
    const float4* Wg1 = (const float4*)(W1 + (size_t)e * DDIM * HDIM);
    const float4* W2g = (const float4*)(W2 + (size_t)e * HDIM * DDIM);

    const int tokA = tid & 31,        kqA = tid >> 5;        // X prefetch slot 0
    const int tokB = tokA,            kqB = kqA + 4;         // X prefetch slot 1 (tid+128)

    float4 xv0, xv1, wv[4];
    // ---- prologue: prefetch chunk 0 ----
    xv0 = Xg[(size_t)toks[tokA] * 64 + 0 + kqA];
    xv1 = Xg[(size_t)toks[tokB] * 64 + 0 + kqB];
#pragma unroll
    for (int i = 0; i < 4; i++) wv[i] = Wg1[tid + i * 128];

    float acc[4][4];
#pragma unroll
    for (int i = 0; i < 4; i++)
#pragma unroll
        for (int j = 0; j < 4; j++) acc[i][j] = 0.f;

    // ================= GEMM1: 8 chunks of K=32 =================
    for (int c = 0; c < 8; c++) {
        const int b = c & 1;
        // STS prefetched chunk c (X transposed scalar, W vector)
        XS(b, kqA * 4 + 0, tokA) = xv0.x;
        XS(b, kqA * 4 + 1, tokA) = xv0.y;
        XS(b, kqA * 4 + 2, tokA) = xv0.z;
        XS(b, kqA * 4 + 3, tokA) = xv0.w;
        XS(b, kqB * 4 + 0, tokB) = xv1.x;
        XS(b, kqB * 4 + 1, tokB) = xv1.y;
        XS(b, kqB * 4 + 2, tokB) = xv1.z;
        XS(b, kqB * 4 + 3, tokB) = xv1.w;
#pragma unroll
        for (int i = 0; i < 4; i++) {
            int lin = tid + i * 128;
            *(float4*)&WB1(b, lin >> 4, (lin & 15) * 4) = wv[i];
        }
        // prefetch chunk c+1
        if (c < 7) {
            int k0 = (c + 1) * 32;
            xv0 = Xg[(size_t)toks[tokA] * 64 + (k0 >> 2) + kqA];
            xv1 = Xg[(size_t)toks[tokB] * 64 + (k0 >> 2) + kqB];
#pragma unroll
            for (int i = 0; i < 4; i++) wv[i] = Wg1[(k0 << 4) + tid + i * 128];
        }
        __syncthreads();
        // compute chunk c
#pragma unroll
        for (int k = 0; k < 32; k++) {
            float4 a = *(const float4*)&XS(b, k, ty * 4);
            float4 bb = *(const float4*)&WB1(b, k, tx * 4);
            float av[4] = {a.x, a.y, a.z, a.w};
            float bv[4] = {bb.x, bb.y, bb.z, bb.w};
#pragma unroll
            for (int i = 0; i < 4; i++)
#pragma unroll
                for (int j = 0; j < 4; j++) acc[i][j] += av[i] * bv[j];
        }
    }

    // bias + relu -> Hs[h][tok]
    {
        float4 bb = *(const float4*)&b1[e * HDIM + tx * 4];
        float bv[4] = {bb.x, bb.y, bb.z, bb.w};
#pragma unroll
        for (int i = 0; i < 4; i++) {
            int tok = ty * 4 + i;
#pragma unroll
            for (int j = 0; j < 4; j++) {
                float v = acc[i][j] + bv[j];
                Hs[tx * 4 + j][tok] = v > 0.f ? v : 0.f;
            }
        }
    }

    // ---- GEMM2 prologue: prefetch W2 chunk 0 (64 cols) ----
    float4 wv2[8];
#pragma unroll
    for (int i = 0; i < 8; i++) {
        int lin = tid + i * 128;                 // 0..1023
        wv2[i] = W2g[(lin >> 4) * 64 + (lin & 15)];
    }
    __syncthreads();   // GEMM1 arena reads + Hs writes complete

    // ================= GEMM2: 4 chunks of 64 output cols =================
    for (int c = 0; c < 4; c++) {
        const int b = c & 1;
#pragma unroll
        for (int i = 0; i < 8; i++) {
            int lin = tid + i * 128;
            *(float4*)&WB2(b, lin >> 4, (lin & 15) * 4) = wv2[i];
        }
        if (c < 3) {
#pragma unroll
            for (int i = 0; i < 8; i++) {
                int lin = tid + i * 128;
                wv2[i] = W2g[(lin >> 4) * 64 + (c + 1) * 16 + (lin & 15)];
            }
        }
        __syncthreads();

#pragma unroll
        for (int i = 0; i < 4; i++)
#pragma unroll
            for (int j = 0; j < 4; j++) acc[i][j] = 0.f;

#pragma unroll 8
        for (int k = 0; k < HDIM; k++) {
            float4 a = *(const float4*)&Hs[k][ty * 4];
            float4 bb = *(const float4*)&WB2(b, k, tx * 4);
            float av[4] = {a.x, a.y, a.z, a.w};
            float bv[4] = {bb.x, bb.y, bb.z, bb.w};
#pragma unroll
            for (int i = 0; i < 4; i++)
#pragma unroll
                for (int j = 0; j < 4; j++) acc[i][j] += av[i] * bv[j];
        }

        // epilogue: bias + relu + store this 64-col chunk
        float4 cb = *(const float4*)&b2[e * DDIM + c * 64 + tx * 4];
#pragma unroll
        for (int i = 0; i < 4; i++) {
            int ti = ty * 4 + i;
            if (ti < nt) {
                size_t row = (size_t)toks[ti] * DDIM;
                float4 r;
                r.x = fmaxf(acc[i][0] + cb.x, 0.f);
                r.y = fmaxf(acc[i][1] + cb.y, 0.f);
                r.z = fmaxf(acc[i][2] + cb.z, 0.f);
                r.w = fmaxf(acc[i][3] + cb.w, 0.f);
                *(float4*)&out[row + c * 64 + tx * 4] = r;
            }
        }
    }
#undef XS
#undef WB1
#undef WB2
}

// ---------------- launch ----------------
extern "C" void kernel_launch(void* const* d_in, const int* in_sizes, int n_in,
                              void* d_out, int out_size) {
    const float* x   = (const float*)d_in[0];
    const float* rw  = (const float*)d_in[1];
    const float* rb  = (const float*)d_in[2];
    const float* W1  = (const float*)d_in[3];
    const float* b1  = (const float*)d_in[4];
    const float* W2  = (const float*)d_in[5];
    const float* b2  = (const float*)d_in[6];
    float* out = (float*)d_out;

    k_router<<<N_TOK / 8, 256>>>(x, rw, rb);
    k_scan<<<1, 32>>>();
    k_scatter<<<N_TOK / 256, 256>>>();
    k_ffn<<<FFN_CTAS, 128>>>(x, W1, b1, W2, b2, out);
}

// round 6
// speedup vs baseline: 2.1085x; 1.0008x over previous
#include <cuda_runtime.h>

#define N_TOK 8192
#define DDIM  256
#define HDIM  64
#define NEXP  32
#define TM    32        // tokens per ffn tile
#define FFN_CTAS 288    // >= max tiles: 8192/32=256 full + <=31 partial tails

typedef unsigned long long u64;

// packed-f32x2 helpers (sm_100+; ptxas never emits FFMA2 from C++)
#define DUP2(d, s)    asm("mov.b64 %0, {%1, %1};" : "=l"(d) : "f"(s))
#define FMA2(c, a, b) asm("fma.rn.f32x2 %0, %1, %2, %0;" : "+l"(c) : "l"(a), "l"(b))
#define UNPK(lo, hi, p) asm("mov.b64 {%0, %1}, %2;" : "=f"(lo), "=f"(hi) : "l"(p))

// ---------------- scratch (no allocations allowed) ----------------
__device__ int g_idx[N_TOK];
__device__ int g_counts[NEXP];     // zero at init; k_scan resets each call
__device__ int g_off[NEXP + 1];
__device__ int g_cursor[NEXP];
__device__ int g_perm[N_TOK];

// ---------------- kernel 1: router + argmax ----------------
__global__ void __launch_bounds__(256) k_router(const float* __restrict__ x,
                                                const float* __restrict__ rw,
                                                const float* __restrict__ rb) {
    int warp = threadIdx.x >> 5;
    int lane = threadIdx.x & 31;
    int n = blockIdx.x * 8 + warp;

    const float4* X4 = (const float4*)x;
    const float4* W4 = (const float4*)rw;

    float4 x0 = X4[n * 64 + lane];
    float4 x1 = X4[n * 64 + 32 + lane];

    float p[NEXP];
#pragma unroll
    for (int e = 0; e < NEXP; e++) {
        float4 w0 = W4[e * 64 + lane];
        float4 w1 = W4[e * 64 + 32 + lane];
        p[e] = x0.x * w0.x + x0.y * w0.y + x0.z * w0.z + x0.w * w0.w
             + x1.x * w1.x + x1.y * w1.y + x1.z * w1.z + x1.w * w1.w;
    }

    // reduce-scatter transpose: lane l ends holding full logit of expert l
#pragma unroll
    for (int off = 16; off > 0; off >>= 1) {
        bool hi = (lane & off) != 0;
#pragma unroll
        for (int i = 0; i < 16; i++) {
            if (i < off) {
                float sel = hi ? p[i] : p[i + off];
                float got = __shfl_xor_sync(0xffffffffu, sel, off);
                p[i] = (hi ? p[i + off] : p[i]) + got;
            }
        }
    }

    float v  = p[0] + rb[lane];
    int   bi = lane;
#pragma unroll
    for (int off = 16; off > 0; off >>= 1) {
        float ov = __shfl_xor_sync(0xffffffffu, v, off);
        int   oi = __shfl_xor_sync(0xffffffffu, bi, off);
        if (ov > v || (ov == v && oi < bi)) { v = ov; bi = oi; }  // first-max
    }

    if (lane == 0) {
        g_idx[n] = bi;
        atomicAdd(&g_counts[bi], 1);   // return unused -> RED
    }
}

// ---------------- kernel 2: 32-entry exclusive scan (1 warp) ----------------
__global__ void k_scan() {
    int lane = threadIdx.x;
    int c = g_counts[lane];
    int s = c;
#pragma unroll
    for (int off = 1; off < 32; off <<= 1) {
        int t = __shfl_up_sync(0xffffffffu, s, off);
        if (lane >= off) s += t;
    }
    g_off[lane]    = s - c;
    g_cursor[lane] = s - c;
    if (lane == 31) g_off[NEXP] = s;
    g_counts[lane] = 0;                // ready for next graph replay
}

// ---------------- kernel 3: scatter (block-aggregated counting sort) ----------------
__global__ void __launch_bounds__(256) k_scatter() {
    __shared__ int hist[NEXP], sbase[NEXP], scur[NEXP];
    int tid = threadIdx.x;
    int n = blockIdx.x * 256 + tid;
    int e = g_idx[n];
    if (tid < NEXP) { hist[tid] = 0; scur[tid] = 0; }
    __syncthreads();
    atomicAdd(&hist[e], 1);
    __syncthreads();
    if (tid < NEXP) sbase[tid] = atomicAdd(&g_cursor[tid], hist[tid]);
    __syncthreads();
    int r = atomicAdd(&scur[e], 1);
    g_perm[sbase[e] + r] = n;
}

// ---------------- kernel 4: grouped expert FFN (pipelined + FFMA2) ----------------
// 288 CTAs x 128 thr, 32 tokens/CTA (2 CTAs/SM). Double-buffered smem arena;
// inner loops use fma.rn.f32x2: accumulators packed along the token dim
// (token pairs come free from the Xs[k][tok] LDS.128), b dup'd per k on the
// alu pipe. fma-pipe issues per k halve: 32 -> 16 per SMSP.
__global__ void __launch_bounds__(128) k_ffn(const float* __restrict__ x,
                                             const float* __restrict__ W1,
                                             const float* __restrict__ b1,
                                             const float* __restrict__ W2,
                                             const float* __restrict__ b2,
                                             float* __restrict__ out) {
    // map blockIdx.x -> (expert e, tile)
    int e = -1, tile = 0;
    {
        int t = blockIdx.x, acc = 0, prev = g_off[0];
#pragma unroll
        for (int ee = 0; ee < NEXP; ee++) {
            int nxt = g_off[ee + 1];
            int tiles_e = (nxt - prev + TM - 1) >> 5;
            if (e < 0 && t < acc + tiles_e) { e = ee; tile = t - acc; }
            acc += tiles_e;
            prev = nxt;
        }
        if (e < 0) return;
    }

    const int off0 = g_off[e];
    const int cnt  = g_off[e + 1] - off0;

    const int tid = threadIdx.x;
    const int tx  = tid & 15;        // 16 h-groups of 4
    const int ty  = tid >> 4;        // 8 token-groups of 4

    int rem = cnt - tile * TM;
    const int nt = rem > TM ? TM : rem;

    __shared__ int   toks[TM];
    __shared__ float Hs[HDIM][36];       // [h][tok], padded
    __shared__ float arena[8192];        // 32KB union (same as round 5)
#define XS(b,k,t)  arena[(b)*1152 + (k)*36 + (t)]
#define WB1(b,k,h) arena[2304 + (b)*2048 + (k)*64 + (h)]
#define WB2(b,k,nn) arena[(b)*4096 + (k)*64 + (nn)]

    if (tid < TM) toks[tid] = g_perm[off0 + min(tile * TM + tid, cnt - 1)];
    __syncthreads();

    const float4* Xg  = (const float4*)x;
    const float4* Wg1 = (const float4*)(W1 + (size_t)e * DDIM * HDIM);
    const float4* W2g = (const float4*)(W2 + (size_t)e * HDIM * DDIM);

    const int tokA = tid & 31,        kqA = tid >> 5;        // X prefetch slot 0
    const int tokB = tokA,            kqB = kqA + 4;         // X prefetch slot 1

    float4 xv0, xv1, wv[4];
    // ---- prologue: prefetch chunk 0 ----
    xv0 = Xg[(size_t)toks[tokA] * 64 + 0 + kqA];
    xv1 = Xg[(size_t)toks[tokB] * 64 + 0 + kqB];
#pragma unroll
    for (int i = 0; i < 4; i++) wv[i] = Wg1[tid + i * 128];

    // packed accumulators: acc2[p][j] = (tok 2p, tok 2p+1) x h(tx*4+j)
    u64 acc2[2][4];
#pragma unroll
    for (int p = 0; p < 2; p++)
#pragma unroll
        for (int j = 0; j < 4; j++) acc2[p][j] = 0ull;

    // ================= GEMM1: 8 chunks of K=32 =================
    for (int c = 0; c < 8; c++) {
        const int b = c & 1;
        XS(b, kqA * 4 + 0, tokA) = xv0.x;
        XS(b, kqA * 4 + 1, tokA) = xv0.y;
        XS(b, kqA * 4 + 2, tokA) = xv0.z;
        XS(b, kqA * 4 + 3, tokA) = xv0.w;
        XS(b, kqB * 4 + 0, tokB) = xv1.x;
        XS(b, kqB * 4 + 1, tokB) = xv1.y;
        XS(b, kqB * 4 + 2, tokB) = xv1.z;
        XS(b, kqB * 4 + 3, tokB) = xv1.w;
#pragma unroll
        for (int i = 0; i < 4; i++) {
            int lin = tid + i * 128;
            *(float4*)&WB1(b, lin >> 4, (lin & 15) * 4) = wv[i];
        }
        if (c < 7) {
            int k0 = (c + 1) * 32;
            xv0 = Xg[(size_t)toks[tokA] * 64 + (k0 >> 2) + kqA];
            xv1 = Xg[(size_t)toks[tokB] * 64 + (k0 >> 2) + kqB];
#pragma unroll
            for (int i = 0; i < 4; i++) wv[i] = Wg1[(k0 << 4) + tid + i * 128];
        }
        __syncthreads();
#pragma unroll
        for (int k = 0; k < 32; k++) {
            ulonglong2 a = *(const ulonglong2*)&XS(b, k, ty * 4);  // (t0,t1),(t2,t3)
            float4 bb = *(const float4*)&WB1(b, k, tx * 4);
            u64 bd0, bd1, bd2, bd3;
            DUP2(bd0, bb.x); DUP2(bd1, bb.y); DUP2(bd2, bb.z); DUP2(bd3, bb.w);
            FMA2(acc2[0][0], a.x, bd0); FMA2(acc2[1][0], a.y, bd0);
            FMA2(acc2[0][1], a.x, bd1); FMA2(acc2[1][1], a.y, bd1);
            FMA2(acc2[0][2], a.x, bd2); FMA2(acc2[1][2], a.y, bd2);
            FMA2(acc2[0][3], a.x, bd3); FMA2(acc2[1][3], a.y, bd3);
        }
    }

    // bias + relu -> Hs[h][tok]
    {
        float4 bb = *(const float4*)&b1[e * HDIM + tx * 4];
        float bv[4] = {bb.x, bb.y, bb.z, bb.w};
#pragma unroll
        for (int p = 0; p < 2; p++) {
#pragma unroll
            for (int j = 0; j < 4; j++) {
                float lo, hi;
                UNPK(lo, hi, acc2[p][j]);
                lo += bv[j]; hi += bv[j];
                Hs[tx * 4 + j][ty * 4 + 2 * p]     = lo > 0.f ? lo : 0.f;
                Hs[tx * 4 + j][ty * 4 + 2 * p + 1] = hi > 0.f ? hi : 0.f;
            }
        }
    }

    // ---- GEMM2 prologue: prefetch W2 chunk 0 ----
    float4 wv2[8];
#pragma unroll
    for (int i = 0; i < 8; i++) {
        int lin = tid + i * 128;
        wv2[i] = W2g[(lin >> 4) * 64 + (lin & 15)];
    }
    __syncthreads();   // GEMM1 arena reads + Hs writes complete

    // ================= GEMM2: 4 chunks of 64 output cols =================
    for (int c = 0; c < 4; c++) {
        const int b = c & 1;
#pragma unroll
        for (int i = 0; i < 8; i++) {
            int lin = tid + i * 128;
            *(float4*)&WB2(b, lin >> 4, (lin & 15) * 4) = wv2[i];
        }
        if (c < 3) {
#pragma unroll
            for (int i = 0; i < 8; i++) {
                int lin = tid + i * 128;
                wv2[i] = W2g[(lin >> 4) * 64 + (c + 1) * 16 + (lin & 15)];
            }
        }
        __syncthreads();

#pragma unroll
        for (int p = 0; p < 2; p++)
#pragma unroll
            for (int j = 0; j < 4; j++) acc2[p][j] = 0ull;

#pragma unroll 8
        for (int k = 0; k < HDIM; k++) {
            ulonglong2 a = *(const ulonglong2*)&Hs[k][ty * 4];
            float4 bb = *(const float4*)&WB2(b, k, tx * 4);
            u64 bd0, bd1, bd2, bd3;
            DUP2(bd0, bb.x); DUP2(bd1, bb.y); DUP2(bd2, bb.z); DUP2(bd3, bb.w);
            FMA2(acc2[0][0], a.x, bd0); FMA2(acc2[1][0], a.y, bd0);
            FMA2(acc2[0][1], a.x, bd1); FMA2(acc2[1][1], a.y, bd1);
            FMA2(acc2[0][2], a.x, bd2); FMA2(acc2[1][2], a.y, bd2);
            FMA2(acc2[0][3], a.x, bd3); FMA2(acc2[1][3], a.y, bd3);
        }

        // epilogue: bias + relu + store this 64-col chunk
        float4 cb = *(const float4*)&b2[e * DDIM + c * 64 + tx * 4];
        float cv[4] = {cb.x, cb.y, cb.z, cb.w};
        float r[4][4];
#pragma unroll
        for (int p = 0; p < 2; p++) {
#pragma unroll
            for (int j = 0; j < 4; j++) {
                float lo, hi;
                UNPK(lo, hi, acc2[p][j]);
                r[2 * p][j]     = fmaxf(lo + cv[j], 0.f);
                r[2 * p + 1][j] = fmaxf(hi + cv[j], 0.f);
            }
        }
#pragma unroll
        for (int i = 0; i < 4; i++) {
            int ti = ty * 4 + i;
            if (ti < nt) {
                size_t row = (size_t)toks[ti] * DDIM;
                float4 rv;
                rv.x = r[i][0]; rv.y = r[i][1]; rv.z = r[i][2]; rv.w = r[i][3];
                *(float4*)&out[row + c * 64 + tx * 4] = rv;
            }
        }
    }
#undef XS
#undef WB1
#undef WB2
}

// ---------------- launch ----------------
extern "C" void kernel_launch(void* const* d_in, const int* in_sizes, int n_in,
                              void* d_out, int out_size) {
    const float* x   = (const float*)d_in[0];
    const float* rw  = (const float*)d_in[1];
    const float* rb  = (const float*)d_in[2];
    const float* W1  = (const float*)d_in[3];
    const float* b1  = (const float*)d_in[4];
    const float* W2  = (const float*)d_in[5];
    const float* b2  = (const float*)d_in[6];
    float* out = (float*)d_out;

    k_router<<<N_TOK / 8, 256>>>(x, rw, rb);
    k_scan<<<1, 32>>>();
    k_scatter<<<N_TOK / 256, 256>>>();
    k_ffn<<<FFN_CTAS, 128>>>(x, W1, b1, W2, b2, out);
}

// round 7
// speedup vs baseline: 2.1643x; 1.0264x over previous
#include <cuda_runtime.h>

#define N_TOK 8192
#define DDIM  256
#define HDIM  64
#define NEXP  32
#define TM    32        // tokens per ffn tile
#define FFN_CTAS 288    // >= max tiles: 8192/32=256 full + <=31 partial tails

typedef unsigned long long u64;

// packed-f32x2 helpers (sm_100+; ptxas never emits FFMA2 from C++)
#define DUP2(d, s)    asm("mov.b64 %0, {%1, %1};" : "=l"(d) : "f"(s))
#define FMA2(c, a, b) asm("fma.rn.f32x2 %0, %1, %2, %0;" : "+l"(c) : "l"(a), "l"(b))
#define UNPK(lo, hi, p) asm("mov.b64 {%0, %1}, %2;" : "=f"(lo), "=f"(hi) : "l"(p))

// ---------------- scratch (no allocations allowed) ----------------
__device__ int g_idx[N_TOK];
__device__ int g_counts[NEXP];     // zero at init; k_scan resets each call
__device__ int g_off[NEXP + 1];
__device__ int g_cursor[NEXP];
__device__ int g_perm[N_TOK];

// ---------------- kernel 1: router as tiled GEMM + fused argmax ----------------
// 128 CTAs x 128 thr. CTA tile: 64 tokens x 32 experts, K=256 (8 chunks of 32,
// reg-prefetch pipelined). Thread tile 4 tok x 4 exp. Epilogue: bias + per-
// thread argmax (strict > = first-max) + 3-round shfl reduce across the 8
// expert-lanes + smem-aggregated histogram.
__global__ void __launch_bounds__(128) k_router(const float* __restrict__ x,
                                                const float* __restrict__ rw,
                                                const float* __restrict__ rb) {
    const int tid = threadIdx.x;
    const int tx  = tid & 7;       // expert group: experts tx*4..tx*4+3
    const int ty  = tid >> 3;      // token group: tokens ty*4..ty*4+3
    const int tok0 = blockIdx.x * 64;

    __shared__ float Xs[32][68];   // [k][tok], stride 68 (16B-aligned rows)
    __shared__ float Ws[32][32];   // [k][exp]
    __shared__ int   hist[NEXP];

    if (tid < NEXP) hist[tid] = 0;

    const float4* Xg = (const float4*)x;
    const float4* Wg = (const float4*)rw;

    // prefetch chunk 0
    float4 xv[4], wv[2];
#pragma unroll
    for (int i = 0; i < 4; i++) {
        int lin = tid + i * 128;            // 0..511
        xv[i] = Xg[(size_t)(tok0 + (lin & 63)) * 64 + (lin >> 6)];
    }
#pragma unroll
    for (int i = 0; i < 2; i++) {
        int lin = tid + i * 128;            // 0..255: e=lin&31, kq=lin>>5
        wv[i] = Wg[(size_t)(lin & 31) * 64 + (lin >> 5)];
    }

    float acc[4][4];
#pragma unroll
    for (int i = 0; i < 4; i++)
#pragma unroll
        for (int j = 0; j < 4; j++) acc[i][j] = 0.f;

    for (int c = 0; c < 8; c++) {
        // STS prefetched chunk (transposed)
#pragma unroll
        for (int i = 0; i < 4; i++) {
            int lin = tid + i * 128;
            int tok = lin & 63, kq = lin >> 6;
            Xs[kq * 4 + 0][tok] = xv[i].x;
            Xs[kq * 4 + 1][tok] = xv[i].y;
            Xs[kq * 4 + 2][tok] = xv[i].z;
            Xs[kq * 4 + 3][tok] = xv[i].w;
        }
#pragma unroll
        for (int i = 0; i < 2; i++) {
            int lin = tid + i * 128;
            int ee = lin & 31, kq = lin >> 5;
            Ws[kq * 4 + 0][ee] = wv[i].x;
            Ws[kq * 4 + 1][ee] = wv[i].y;
            Ws[kq * 4 + 2][ee] = wv[i].z;
            Ws[kq * 4 + 3][ee] = wv[i].w;
        }
        __syncthreads();
        // prefetch chunk c+1
        if (c < 7) {
            int kq0 = (c + 1) * 8;
#pragma unroll
            for (int i = 0; i < 4; i++) {
                int lin = tid + i * 128;
                xv[i] = Xg[(size_t)(tok0 + (lin & 63)) * 64 + kq0 + (lin >> 6)];
            }
#pragma unroll
            for (int i = 0; i < 2; i++) {
                int lin = tid + i * 128;
                wv[i] = Wg[(size_t)(lin & 31) * 64 + kq0 + (lin >> 5)];
            }
        }
        // compute chunk c
#pragma unroll
        for (int k = 0; k < 32; k++) {
            float4 a = *(const float4*)&Xs[k][ty * 4];
            float4 b = *(const float4*)&Ws[k][tx * 4];
            float av[4] = {a.x, a.y, a.z, a.w};
            float bv[4] = {b.x, b.y, b.z, b.w};
#pragma unroll
            for (int i = 0; i < 4; i++)
#pragma unroll
                for (int j = 0; j < 4; j++) acc[i][j] += av[i] * bv[j];
        }
        __syncthreads();
    }

    // epilogue: bias + argmax
    float4 rbv4 = *(const float4*)&rb[tx * 4];
    float rbv[4] = {rbv4.x, rbv4.y, rbv4.z, rbv4.w};
#pragma unroll
    for (int i = 0; i < 4; i++) {
        float v = acc[i][0] + rbv[0];
        int idx = tx * 4;
#pragma unroll
        for (int j = 1; j < 4; j++) {
            float val = acc[i][j] + rbv[j];
            if (val > v) { v = val; idx = tx * 4 + j; }   // strict > = first-max
        }
        // reduce across the 8 expert-lanes (tx = low 3 bits of lane id)
#pragma unroll
        for (int m = 1; m < 8; m <<= 1) {
            float ov = __shfl_xor_sync(0xffffffffu, v, m);
            int   oi = __shfl_xor_sync(0xffffffffu, idx, m);
            if (ov > v || (ov == v && oi < idx)) { v = ov; idx = oi; }
        }
        if (tx == 0) {
            g_idx[tok0 + ty * 4 + i] = idx;
            atomicAdd(&hist[idx], 1);
        }
    }
    __syncthreads();
    if (tid < NEXP && hist[tid]) atomicAdd(&g_counts[tid], hist[tid]);
}

// ---------------- kernel 2: 32-entry exclusive scan (1 warp) ----------------
__global__ void k_scan() {
    int lane = threadIdx.x;
    int c = g_counts[lane];
    int s = c;
#pragma unroll
    for (int off = 1; off < 32; off <<= 1) {
        int t = __shfl_up_sync(0xffffffffu, s, off);
        if (lane >= off) s += t;
    }
    g_off[lane]    = s - c;
    g_cursor[lane] = s - c;
    if (lane == 31) g_off[NEXP] = s;
    g_counts[lane] = 0;                // ready for next graph replay
}

// ---------------- kernel 3: scatter (block-aggregated counting sort) ----------------
__global__ void __launch_bounds__(256) k_scatter() {
    __shared__ int hist[NEXP], sbase[NEXP], scur[NEXP];
    int tid = threadIdx.x;
    int n = blockIdx.x * 256 + tid;
    int e = g_idx[n];
    if (tid < NEXP) { hist[tid] = 0; scur[tid] = 0; }
    __syncthreads();
    atomicAdd(&hist[e], 1);
    __syncthreads();
    if (tid < NEXP) sbase[tid] = atomicAdd(&g_cursor[tid], hist[tid]);
    __syncthreads();
    int r = atomicAdd(&scur[e], 1);
    g_perm[sbase[e] + r] = n;
}

// ---------------- kernel 4: grouped expert FFN (pipelined + FFMA2) ----------------
__global__ void __launch_bounds__(128) k_ffn(const float* __restrict__ x,
                                             const float* __restrict__ W1,
                                             const float* __restrict__ b1,
                                             const float* __restrict__ W2,
                                             const float* __restrict__ b2,
                                             float* __restrict__ out) {
    // map blockIdx.x -> (expert e, tile)
    int e = -1, tile = 0;
    {
        int t = blockIdx.x, acc = 0, prev = g_off[0];
#pragma unroll
        for (int ee = 0; ee < NEXP; ee++) {
            int nxt = g_off[ee + 1];
            int tiles_e = (nxt - prev + TM - 1) >> 5;
            if (e < 0 && t < acc + tiles_e) { e = ee; tile = t - acc; }
            acc += tiles_e;
            prev = nxt;
        }
        if (e < 0) return;
    }

    const int off0 = g_off[e];
    const int cnt  = g_off[e + 1] - off0;

    const int tid = threadIdx.x;
    const int tx  = tid & 15;        // 16 h-groups of 4
    const int ty  = tid >> 4;        // 8 token-groups of 4

    int rem = cnt - tile * TM;
    const int nt = rem > TM ? TM : rem;

    __shared__ int   toks[TM];
    __shared__ float Hs[HDIM][36];       // [h][tok], padded
    __shared__ float arena[8192];        // 32KB union
#define XS(b,k,t)  arena[(b)*1152 + (k)*36 + (t)]
#define WB1(b,k,h) arena[2304 + (b)*2048 + (k)*64 + (h)]
#define WB2(b,k,nn) arena[(b)*4096 + (k)*64 + (nn)]

    if (tid < TM) toks[tid] = g_perm[off0 + min(tile * TM + tid, cnt - 1)];
    __syncthreads();

    const float4* Xg  = (const float4*)x;
    const float4* Wg1 = (const float4*)(W1 + (size_t)e * DDIM * HDIM);
    const float4* W2g = (const float4*)(W2 + (size_t)e * HDIM * DDIM);

    const int tokA = tid & 31,        kqA = tid >> 5;
    const int tokB = tokA,            kqB = kqA + 4;

    float4 xv0, xv1, wv[4];
    xv0 = Xg[(size_t)toks[tokA] * 64 + 0 + kqA];
    xv1 = Xg[(size_t)toks[tokB] * 64 + 0 + kqB];
#pragma unroll
    for (int i = 0; i < 4; i++) wv[i] = Wg1[tid + i * 128];

    u64 acc2[2][4];
#pragma unroll
    for (int p = 0; p < 2; p++)
#pragma unroll
        for (int j = 0; j < 4; j++) acc2[p][j] = 0ull;

    // ================= GEMM1: 8 chunks of K=32 =================
    for (int c = 0; c < 8; c++) {
        const int b = c & 1;
        XS(b, kqA * 4 + 0, tokA) = xv0.x;
        XS(b, kqA * 4 + 1, tokA) = xv0.y;
        XS(b, kqA * 4 + 2, tokA) = xv0.z;
        XS(b, kqA * 4 + 3, tokA) = xv0.w;
        XS(b, kqB * 4 + 0, tokB) = xv1.x;
        XS(b, kqB * 4 + 1, tokB) = xv1.y;
        XS(b, kqB * 4 + 2, tokB) = xv1.z;
        XS(b, kqB * 4 + 3, tokB) = xv1.w;
#pragma unroll
        for (int i = 0; i < 4; i++) {
            int lin = tid + i * 128;
            *(float4*)&WB1(b, lin >> 4, (lin & 15) * 4) = wv[i];
        }
        if (c < 7) {
            int k0 = (c + 1) * 32;
            xv0 = Xg[(size_t)toks[tokA] * 64 + (k0 >> 2) + kqA];
            xv1 = Xg[(size_t)toks[tokB] * 64 + (k0 >> 2) + kqB];
#pragma unroll
            for (int i = 0; i < 4; i++) wv[i] = Wg1[(k0 << 4) + tid + i * 128];
        }
        __syncthreads();
#pragma unroll
        for (int k = 0; k < 32; k++) {
            ulonglong2 a = *(const ulonglong2*)&XS(b, k, ty * 4);
            float4 bb = *(const float4*)&WB1(b, k, tx * 4);
            u64 bd0, bd1, bd2, bd3;
            DUP2(bd0, bb.x); DUP2(bd1, bb.y); DUP2(bd2, bb.z); DUP2(bd3, bb.w);
            FMA2(acc2[0][0], a.x, bd0); FMA2(acc2[1][0], a.y, bd0);
            FMA2(acc2[0][1], a.x, bd1); FMA2(acc2[1][1], a.y, bd1);
            FMA2(acc2[0][2], a.x, bd2); FMA2(acc2[1][2], a.y, bd2);
            FMA2(acc2[0][3], a.x, bd3); FMA2(acc2[1][3], a.y, bd3);
        }
    }

    // bias + relu -> Hs[h][tok]
    {
        float4 bb = *(const float4*)&b1[e * HDIM + tx * 4];
        float bv[4] = {bb.x, bb.y, bb.z, bb.w};
#pragma unroll
        for (int p = 0; p < 2; p++) {
#pragma unroll
            for (int j = 0; j < 4; j++) {
                float lo, hi;
                UNPK(lo, hi, acc2[p][j]);
                lo += bv[j]; hi += bv[j];
                Hs[tx * 4 + j][ty * 4 + 2 * p]     = lo > 0.f ? lo : 0.f;
                Hs[tx * 4 + j][ty * 4 + 2 * p + 1] = hi > 0.f ? hi : 0.f;
            }
        }
    }

    float4 wv2[8];
#pragma unroll
    for (int i = 0; i < 8; i++) {
        int lin = tid + i * 128;
        wv2[i] = W2g[(lin >> 4) * 64 + (lin & 15)];
    }
    __syncthreads();

    // ================= GEMM2: 4 chunks of 64 output cols =================
    for (int c = 0; c < 4; c++) {
        const int b = c & 1;
#pragma unroll
        for (int i = 0; i < 8; i++) {
            int lin = tid + i * 128;
            *(float4*)&WB2(b, lin >> 4, (lin & 15) * 4) = wv2[i];
        }
        if (c < 3) {
#pragma unroll
            for (int i = 0; i < 8; i++) {
                int lin = tid + i * 128;
                wv2[i] = W2g[(lin >> 4) * 64 + (c + 1) * 16 + (lin & 15)];
            }
        }
        __syncthreads();

#pragma unroll
        for (int p = 0; p < 2; p++)
#pragma unroll
            for (int j = 0; j < 4; j++) acc2[p][j] = 0ull;

#pragma unroll 8
        for (int k = 0; k < HDIM; k++) {
            ulonglong2 a = *(const ulonglong2*)&Hs[k][ty * 4];
            float4 bb = *(const float4*)&WB2(b, k, tx * 4);
            u64 bd0, bd1, bd2, bd3;
            DUP2(bd0, bb.x); DUP2(bd1, bb.y); DUP2(bd2, bb.z); DUP2(bd3, bb.w);
            FMA2(acc2[0][0], a.x, bd0); FMA2(acc2[1][0], a.y, bd0);
            FMA2(acc2[0][1], a.x, bd1); FMA2(acc2[1][1], a.y, bd1);
            FMA2(acc2[0][2], a.x, bd2); FMA2(acc2[1][2], a.y, bd2);
            FMA2(acc2[0][3], a.x, bd3); FMA2(acc2[1][3], a.y, bd3);
        }

        float4 cb = *(const float4*)&b2[e * DDIM + c * 64 + tx * 4];
        float cv[4] = {cb.x, cb.y, cb.z, cb.w};
        float r[4][4];
#pragma unroll
        for (int p = 0; p < 2; p++) {
#pragma unroll
            for (int j = 0; j < 4; j++) {
                float lo, hi;
                UNPK(lo, hi, acc2[p][j]);
                r[2 * p][j]     = fmaxf(lo + cv[j], 0.f);
                r[2 * p + 1][j] = fmaxf(hi + cv[j], 0.f);
            }
        }
#pragma unroll
        for (int i = 0; i < 4; i++) {
            int ti = ty * 4 + i;
            if (ti < nt) {
                size_t row = (size_t)toks[ti] * DDIM;
                float4 rv;
                rv.x = r[i][0]; rv.y = r[i][1]; rv.z = r[i][2]; rv.w = r[i][3];
                *(float4*)&out[row + c * 64 + tx * 4] = rv;
            }
        }
    }
#undef XS
#undef WB1
#undef WB2
}

// ---------------- launch ----------------
extern "C" void kernel_launch(void* const* d_in, const int* in_sizes, int n_in,
                              void* d_out, int out_size) {
    const float* x   = (const float*)d_in[0];
    const float* rw  = (const float*)d_in[1];
    const float* rb  = (const float*)d_in[2];
    const float* W1  = (const float*)d_in[3];
    const float* b1  = (const float*)d_in[4];
    const float* W2  = (const float*)d_in[5];
    const float* b2  = (const float*)d_in[6];
    float* out = (float*)d_out;

    k_router<<<N_TOK / 64, 128>>>(x, rw, rb);
    k_scan<<<1, 32>>>();
    k_scatter<<<N_TOK / 256, 256>>>();
    k_ffn<<<FFN_CTAS, 128>>>(x, W1, b1, W2, b2, out);
}